// round 7
// baseline (speedup 1.0000x reference)
#include <cuda_runtime.h>
#include <math.h>

#define BSZ 2
#define SEQ 2048
#define EMB 1024
#define NH  16
#define NKV 4
#define HDM 64
#define WIN 256

// ---------------- scratch (no allocations allowed) ----------------
__device__ float g_qp[BSZ*SEQ*EMB];        // x @ Wq^T
__device__ float g_kp[BSZ*SEQ*NKV*HDM];    // x @ Wk^T
__device__ float g_vp[BSZ*SEQ*NKV*HDM];    // x @ Wv^T
__device__ float g_q [BSZ*NH*SEQ*HDM];     // normed+roped+scaled q  [b][h][s][d]
__device__ float g_k [BSZ*NKV*SEQ*HDM];    // normed+roped k         [b][g][s][d]
__device__ float g_y [BSZ*NH*SEQ*HDM];     // attention out          [b][h][s][d]
__device__ float g_ymix[BSZ*SEQ*EMB];      // pair-mixed, [b][s][h*64+d]
__device__ float g_cos[SEQ*32];
__device__ float g_sin[SEQ*32];

// ---------------- rope tables (double precision) ----------------
__global__ void rope_table_kernel() {
    int idx = blockIdx.x * blockDim.x + threadIdx.x;
    if (idx >= SEQ * 32) return;
    int s = idx >> 5, l = idx & 31;
    // inv_freq = 10000^(-l/32)
    double inv = exp(-(double)l * (9.210340371976184 / 32.0)); // ln(10000)
    double a = (double)s * inv;
    g_cos[idx] = (float)cos(a);
    g_sin[idx] = (float)sin(a);
}

// ---------------- generic C[M,N] = A[M,K] @ W[N,K]^T ----------------
// 64x64 tile, BK=16, 256 threads, 4x4 register blocking.
__global__ __launch_bounds__(256) void gemm64(
    const float* __restrict__ A, const float* __restrict__ W,
    float* __restrict__ C, int M, int N, int K)
{
    __shared__ float As[16][64];   // [k][m]
    __shared__ float Ws[16][64];   // [k][n]
    const int tid  = threadIdx.x;
    const int trow = tid >> 4, tcol = tid & 15;
    const int m0 = blockIdx.y << 6, n0 = blockIdx.x << 6;
    const int lr = tid >> 2;              // 0..63
    const int lk = (tid & 3) << 2;        // 0,4,8,12
    const float* Ap = A + (size_t)(m0 + lr) * K + lk;
    const float* Wp = W + (size_t)(n0 + lr) * K + lk;

    float acc[4][4] = {};
    for (int k0 = 0; k0 < K; k0 += 16) {
        float4 a = *(const float4*)(Ap + k0);
        float4 w = *(const float4*)(Wp + k0);
        __syncthreads();
        As[lk+0][lr] = a.x; As[lk+1][lr] = a.y; As[lk+2][lr] = a.z; As[lk+3][lr] = a.w;
        Ws[lk+0][lr] = w.x; Ws[lk+1][lr] = w.y; Ws[lk+2][lr] = w.z; Ws[lk+3][lr] = w.w;
        __syncthreads();
#pragma unroll
        for (int kk = 0; kk < 16; kk++) {
            float4 av = *(const float4*)&As[kk][trow << 2];
            float4 wv = *(const float4*)&Ws[kk][tcol << 2];
            float qa[4] = {av.x, av.y, av.z, av.w};
            float wa[4] = {wv.x, wv.y, wv.z, wv.w};
#pragma unroll
            for (int i = 0; i < 4; i++)
#pragma unroll
                for (int j = 0; j < 4; j++)
                    acc[i][j] += qa[i] * wa[j];
        }
    }
#pragma unroll
    for (int i = 0; i < 4; i++) {
        float4 o = make_float4(acc[i][0], acc[i][1], acc[i][2], acc[i][3]);
        *(float4*)&C[(size_t)(m0 + (trow << 2) + i) * N + n0 + (tcol << 2)] = o;
    }
}

// ---------------- rmsnorm + rope + gain  (one warp per head-vector) -------
__global__ __launch_bounds__(256) void prep_kernel(const float* __restrict__ qgain)
{
    const int gw   = (blockIdx.x * 256 + threadIdx.x) >> 5;
    const int lane = threadIdx.x & 31;
    const int NQ = BSZ * SEQ * NH;          // 65536
    const int NK = BSZ * SEQ * NKV;         // 16384

    const float* in; float* out; float extra; int s;
    if (gw < NQ) {
        int h = gw & 15; int bs = gw >> 4;
        s = bs & (SEQ - 1); int b = bs >> 11;
        in  = g_qp + (size_t)bs * EMB + h * HDM;
        out = g_q  + ((size_t)(b * NH + h) * SEQ + s) * HDM;
        extra = qgain[h] * 0.125f;          // fold 1/sqrt(64) attention scale
    } else {
        int kw = gw - NQ;
        if (kw >= NK) return;
        int g = kw & 3; int bs = kw >> 2;
        s = bs & (SEQ - 1); int b = bs >> 11;
        in  = g_kp + (size_t)bs * (NKV * HDM) + g * HDM;
        out = g_k  + ((size_t)(b * NKV + g) * SEQ + s) * HDM;
        extra = 1.f;
    }
    float v1 = in[lane], v2 = in[lane + 32];
    float ss = v1 * v1 + v2 * v2;
#pragma unroll
    for (int o = 16; o; o >>= 1) ss += __shfl_xor_sync(0xffffffffu, ss, o);
    float r = rsqrtf(ss * (1.f / HDM) + 1e-6f) * extra;
    float c  = g_cos[s * 32 + lane];
    float sn = g_sin[s * 32 + lane];
    out[lane]      = (v1 * c + v2 * sn) * r;    // v1*cos + v2*sin
    out[lane + 32] = (v2 * c - v1 * sn) * r;    // -v1*sin + v2*cos
}

// ---------------- windowed flash attention ----------------
// grid (S/64, B*H), block 256. smem: Qt|Kt|Vs (d-major/row-major) + P.
__global__ __launch_bounds__(256) void attn_kernel()
{
    extern __shared__ float sm[];
    float* Qt = sm;            // Qt[d*64 + r]
    float* Kt = sm + 4096;     // Kt[d*64 + c]
    float* Vs = sm + 8192;     // Vs[c*64 + dv]
    float* Ps = sm + 12288;    // Ps[r*68 + c]

    const int tid  = threadIdx.x;
    const int trow = tid >> 4, tcol = tid & 15;
    const int bh = blockIdx.y;
    const int b = bh >> 4, h = bh & 15, g = h >> 2;
    const int q0 = blockIdx.x << 6;

    // load Q tile (transpose to d-major)
    const float* Qg = g_q + ((size_t)(b * NH + h) * SEQ + q0) * HDM;
    for (int idx = tid; idx < 1024; idx += 256) {
        int r = idx >> 4, d = (idx & 15) << 2;
        float4 v = *(const float4*)(Qg + r * HDM + d);
        Qt[(d+0)*64 + r] = v.x; Qt[(d+1)*64 + r] = v.y;
        Qt[(d+2)*64 + r] = v.z; Qt[(d+3)*64 + r] = v.w;
    }

    float m[4], l[4], O[4][4];
#pragma unroll
    for (int i = 0; i < 4; i++) {
        m[i] = -1e30f; l[i] = 0.f;
#pragma unroll
        for (int j = 0; j < 4; j++) O[i][j] = 0.f;
    }
    const int qrow = q0 + (trow << 2);
    const float* Kg0 = g_k  + (size_t)(b * NKV + g) * SEQ * HDM;
    const float* Vg0 = g_vp + (size_t)b * SEQ * (NKV * HDM) + g * HDM;

    for (int kt0 = q0 - 256; kt0 <= q0; kt0 += 64) {
        if (kt0 < 0) continue;
        __syncthreads();   // previous PV done before overwriting K/V/P
        const float* Kg = Kg0 + (size_t)kt0 * HDM;
        const float* Vg = Vg0 + (size_t)kt0 * (NKV * HDM);
        for (int idx = tid; idx < 1024; idx += 256) {
            int c = idx >> 4, d = (idx & 15) << 2;
            float4 kv = *(const float4*)(Kg + c * HDM + d);
            Kt[(d+0)*64 + c] = kv.x; Kt[(d+1)*64 + c] = kv.y;
            Kt[(d+2)*64 + c] = kv.z; Kt[(d+3)*64 + c] = kv.w;
            *(float4*)&Vs[c * 64 + d] = *(const float4*)(Vg + c * (NKV * HDM) + d);
        }
        __syncthreads();

        // S = Q K^T (scale folded into q)
        float s4[4][4] = {};
#pragma unroll 16
        for (int d = 0; d < 64; d++) {
            float4 qv = *(const float4*)&Qt[d * 64 + (trow << 2)];
            float4 kv = *(const float4*)&Kt[d * 64 + (tcol << 2)];
            float qa[4] = {qv.x, qv.y, qv.z, qv.w};
            float ka[4] = {kv.x, kv.y, kv.z, kv.w};
#pragma unroll
            for (int i = 0; i < 4; i++)
#pragma unroll
                for (int j = 0; j < 4; j++)
                    s4[i][j] += qa[i] * ka[j];
        }

        // mask + online softmax (row groups of 16 lanes share trow)
        const int kb = kt0 + (tcol << 2);
#pragma unroll
        for (int i = 0; i < 4; i++) {
            int q = qrow + i;
#pragma unroll
            for (int j = 0; j < 4; j++) {
                int kk = kb + j;
                if (kk > q || q - kk >= WIN) s4[i][j] = -1e30f;
            }
            float t = fmaxf(fmaxf(s4[i][0], s4[i][1]), fmaxf(s4[i][2], s4[i][3]));
#pragma unroll
            for (int o = 1; o < 16; o <<= 1)
                t = fmaxf(t, __shfl_xor_sync(0xffffffffu, t, o));
            float mn  = fmaxf(m[i], t);
            float fac = __expf(m[i] - mn);
            m[i] = mn;
            float su = 0.f;
#pragma unroll
            for (int j = 0; j < 4; j++) {
                float p = (s4[i][j] > -1e29f) ? __expf(s4[i][j] - mn) : 0.f;
                s4[i][j] = p;
                su += p;
            }
#pragma unroll
            for (int o = 1; o < 16; o <<= 1)
                su += __shfl_xor_sync(0xffffffffu, su, o);
            l[i] = l[i] * fac + su;
#pragma unroll
            for (int j = 0; j < 4; j++) O[i][j] *= fac;
        }

        // stage P (row-major, stride 68, float4 writes conflict-free)
#pragma unroll
        for (int i = 0; i < 4; i++)
            *(float4*)&Ps[((trow << 2) + i) * 68 + (tcol << 2)] =
                make_float4(s4[i][0], s4[i][1], s4[i][2], s4[i][3]);
        __syncthreads();

        // O += P V
#pragma unroll 8
        for (int c = 0; c < 64; c++) {
            float4 vv = *(const float4*)&Vs[c * 64 + (tcol << 2)];
            float va[4] = {vv.x, vv.y, vv.z, vv.w};
            float pa[4];
#pragma unroll
            for (int i = 0; i < 4; i++) pa[i] = Ps[((trow << 2) + i) * 68 + c];
#pragma unroll
            for (int i = 0; i < 4; i++)
#pragma unroll
                for (int j = 0; j < 4; j++)
                    O[i][j] += pa[i] * va[j];
        }
    }

    float* Yg = g_y + ((size_t)(b * NH + h) * SEQ + qrow) * HDM + (tcol << 2);
#pragma unroll
    for (int i = 0; i < 4; i++) {
        float inv = 1.f / l[i];
        *(float4*)(Yg + (size_t)i * HDM) =
            make_float4(O[i][0]*inv, O[i][1]*inv, O[i][2]*inv, O[i][3]*inv);
    }
}

// ---------------- pair mix:  y_out[2p+o] = sum_i pm[p][o][i]*y[2p+i] ------
__global__ __launch_bounds__(256) void pairmix_kernel(const float* __restrict__ pm)
{
    int idx = blockIdx.x * 256 + threadIdx.x;   // over BSZ*SEQ*EMB
    int d  = idx & 63;
    int h  = (idx >> 6) & 15;
    int bs = idx >> 10;
    int b  = bs >> 11;
    int s  = bs & (SEQ - 1);
    int p  = h >> 1, o = h & 1;
    size_t base = ((size_t)(b * NH + (p << 1)) * SEQ + s) * HDM + d;
    float y0 = g_y[base];
    float y1 = g_y[base + (size_t)SEQ * HDM];
    g_ymix[idx] = pm[(p << 2) + (o << 1)] * y0 + pm[(p << 2) + (o << 1) + 1] * y1;
}

// ---------------- launch ----------------
extern "C" void kernel_launch(void* const* d_in, const int* in_sizes, int n_in,
                              void* d_out, int out_size)
{
    const float* x     = (const float*)d_in[0];
    const float* Wq    = (const float*)d_in[1];
    const float* Wk    = (const float*)d_in[2];
    const float* Wv    = (const float*)d_in[3];
    const float* Wo    = (const float*)d_in[4];
    const float* qgain = (const float*)d_in[5];
    const float* pm    = (const float*)d_in[6];
    float* out = (float*)d_out;

    void *qp, *kp, *vp, *ymix;
    cudaGetSymbolAddress(&qp,   g_qp);
    cudaGetSymbolAddress(&kp,   g_kp);
    cudaGetSymbolAddress(&vp,   g_vp);
    cudaGetSymbolAddress(&ymix, g_ymix);

    const int ATTN_SMEM = (4096 * 3 + 64 * 68) * 4;   // 66560 B
    cudaFuncSetAttribute(attn_kernel, cudaFuncAttributeMaxDynamicSharedMemorySize,
                         ATTN_SMEM);

    const int M = BSZ * SEQ;                 // 4096

    rope_table_kernel<<<SEQ * 32 / 256, 256>>>();
    gemm64<<<dim3(EMB / 64, M / 64), 256>>>(x, Wq, (float*)qp, M, EMB, EMB);
    gemm64<<<dim3(NKV * HDM / 64, M / 64), 256>>>(x, Wk, (float*)kp, M, NKV * HDM, EMB);
    gemm64<<<dim3(NKV * HDM / 64, M / 64), 256>>>(x, Wv, (float*)vp, M, NKV * HDM, EMB);
    prep_kernel<<<(BSZ * SEQ * (NH + NKV) * 32) / 256, 256>>>(qgain);
    attn_kernel<<<dim3(SEQ / 64, BSZ * NH), 256, ATTN_SMEM>>>();
    pairmix_kernel<<<(BSZ * SEQ * EMB) / 256, 256>>>(pm);
    gemm64<<<dim3(EMB / 64, M / 64), 256>>>((const float*)ymix, Wo, out, M, EMB, EMB);
}

// round 8
// speedup vs baseline: 1.0032x; 1.0032x over previous
#include <cuda_runtime.h>
#include <math.h>

#define BSZ 2
#define SEQ 2048
#define EMB 1024
#define NH  16
#define NKV 4
#define HDM 64
#define WIN 256

// ---------------- scratch (no allocations allowed) ----------------
__device__ float g_qp[BSZ*SEQ*EMB];        // x @ Wq^T
__device__ float g_kp[BSZ*SEQ*NKV*HDM];    // x @ Wk^T
__device__ float g_vp[BSZ*SEQ*NKV*HDM];    // x @ Wv^T
__device__ float g_q [BSZ*NH*SEQ*HDM];     // normed+roped+scaled q  [b][h][s][d]
__device__ float g_k [BSZ*NKV*SEQ*HDM];    // normed+roped k         [b][g][s][d]
__device__ float g_y [BSZ*NH*SEQ*HDM];     // attention out          [b][h][s][d]
__device__ float g_ymix[BSZ*SEQ*EMB];      // pair-mixed, [b][s][h*64+d]
__device__ float g_cos[SEQ*32];
__device__ float g_sin[SEQ*32];

// ---------------- rope tables (double precision) ----------------
__global__ void rope_table_kernel() {
    int idx = blockIdx.x * blockDim.x + threadIdx.x;
    if (idx >= SEQ * 32) return;
    int s = idx >> 5, l = idx & 31;
    // inv_freq = 10000^(-l/32)
    double inv = exp(-(double)l * (9.210340371976184 / 32.0)); // ln(10000)
    double a = (double)s * inv;
    g_cos[idx] = (float)cos(a);
    g_sin[idx] = (float)sin(a);
}

// ---------------- generic C[M,N] = A[M,K] @ W[N,K]^T ----------------
// 64x64 tile, BK=16, 256 threads, 4x4 register blocking.
__global__ __launch_bounds__(256) void gemm64(
    const float* __restrict__ A, const float* __restrict__ W,
    float* __restrict__ C, int M, int N, int K)
{
    __shared__ float As[16][64];   // [k][m]
    __shared__ float Ws[16][64];   // [k][n]
    const int tid  = threadIdx.x;
    const int trow = tid >> 4, tcol = tid & 15;
    const int m0 = blockIdx.y << 6, n0 = blockIdx.x << 6;
    const int lr = tid >> 2;              // 0..63
    const int lk = (tid & 3) << 2;        // 0,4,8,12
    const float* Ap = A + (size_t)(m0 + lr) * K + lk;
    const float* Wp = W + (size_t)(n0 + lr) * K + lk;

    float acc[4][4] = {};
    for (int k0 = 0; k0 < K; k0 += 16) {
        float4 a = *(const float4*)(Ap + k0);
        float4 w = *(const float4*)(Wp + k0);
        __syncthreads();
        As[lk+0][lr] = a.x; As[lk+1][lr] = a.y; As[lk+2][lr] = a.z; As[lk+3][lr] = a.w;
        Ws[lk+0][lr] = w.x; Ws[lk+1][lr] = w.y; Ws[lk+2][lr] = w.z; Ws[lk+3][lr] = w.w;
        __syncthreads();
#pragma unroll
        for (int kk = 0; kk < 16; kk++) {
            float4 av = *(const float4*)&As[kk][trow << 2];
            float4 wv = *(const float4*)&Ws[kk][tcol << 2];
            float qa[4] = {av.x, av.y, av.z, av.w};
            float wa[4] = {wv.x, wv.y, wv.z, wv.w};
#pragma unroll
            for (int i = 0; i < 4; i++)
#pragma unroll
                for (int j = 0; j < 4; j++)
                    acc[i][j] += qa[i] * wa[j];
        }
    }
#pragma unroll
    for (int i = 0; i < 4; i++) {
        float4 o = make_float4(acc[i][0], acc[i][1], acc[i][2], acc[i][3]);
        *(float4*)&C[(size_t)(m0 + (trow << 2) + i) * N + n0 + (tcol << 2)] = o;
    }
}

// ---------------- rmsnorm + rope + gain  (one warp per head-vector) -------
__global__ __launch_bounds__(256) void prep_kernel(const float* __restrict__ qgain)
{
    const int gw   = (blockIdx.x * 256 + threadIdx.x) >> 5;
    const int lane = threadIdx.x & 31;
    const int NQ = BSZ * SEQ * NH;          // 65536
    const int NK = BSZ * SEQ * NKV;         // 16384

    const float* in; float* out; float extra; int s;
    if (gw < NQ) {
        int h = gw & 15; int bs = gw >> 4;
        s = bs & (SEQ - 1); int b = bs >> 11;
        in  = g_qp + (size_t)bs * EMB + h * HDM;
        out = g_q  + ((size_t)(b * NH + h) * SEQ + s) * HDM;
        extra = qgain[h] * 0.125f;          // fold 1/sqrt(64) attention scale
    } else {
        int kw = gw - NQ;
        if (kw >= NK) return;
        int g = kw & 3; int bs = kw >> 2;
        s = bs & (SEQ - 1); int b = bs >> 11;
        in  = g_kp + (size_t)bs * (NKV * HDM) + g * HDM;
        out = g_k  + ((size_t)(b * NKV + g) * SEQ + s) * HDM;
        extra = 1.f;
    }
    float v1 = in[lane], v2 = in[lane + 32];
    float ss = v1 * v1 + v2 * v2;
#pragma unroll
    for (int o = 16; o; o >>= 1) ss += __shfl_xor_sync(0xffffffffu, ss, o);
    float r = rsqrtf(ss * (1.f / HDM) + 1e-6f) * extra;
    float c  = g_cos[s * 32 + lane];
    float sn = g_sin[s * 32 + lane];
    out[lane]      = (v1 * c + v2 * sn) * r;    // v1*cos + v2*sin
    out[lane + 32] = (v2 * c - v1 * sn) * r;    // -v1*sin + v2*cos
}

// ---------------- windowed flash attention ----------------
// grid (S/64, B*H), block 256. smem: Qt|Kt|Vs (d-major/row-major) + P.
__global__ __launch_bounds__(256) void attn_kernel()
{
    extern __shared__ float sm[];
    float* Qt = sm;            // Qt[d*64 + r]
    float* Kt = sm + 4096;     // Kt[d*64 + c]
    float* Vs = sm + 8192;     // Vs[c*64 + dv]
    float* Ps = sm + 12288;    // Ps[r*68 + c]

    const int tid  = threadIdx.x;
    const int trow = tid >> 4, tcol = tid & 15;
    const int bh = blockIdx.y;
    const int b = bh >> 4, h = bh & 15, g = h >> 2;
    const int q0 = blockIdx.x << 6;

    // load Q tile (transpose to d-major)
    const float* Qg = g_q + ((size_t)(b * NH + h) * SEQ + q0) * HDM;
    for (int idx = tid; idx < 1024; idx += 256) {
        int r = idx >> 4, d = (idx & 15) << 2;
        float4 v = *(const float4*)(Qg + r * HDM + d);
        Qt[(d+0)*64 + r] = v.x; Qt[(d+1)*64 + r] = v.y;
        Qt[(d+2)*64 + r] = v.z; Qt[(d+3)*64 + r] = v.w;
    }

    float m[4], l[4], O[4][4];
#pragma unroll
    for (int i = 0; i < 4; i++) {
        m[i] = -1e30f; l[i] = 0.f;
#pragma unroll
        for (int j = 0; j < 4; j++) O[i][j] = 0.f;
    }
    const int qrow = q0 + (trow << 2);
    const float* Kg0 = g_k  + (size_t)(b * NKV + g) * SEQ * HDM;
    const float* Vg0 = g_vp + (size_t)b * SEQ * (NKV * HDM) + g * HDM;

    for (int kt0 = q0 - 256; kt0 <= q0; kt0 += 64) {
        if (kt0 < 0) continue;
        __syncthreads();   // previous PV done before overwriting K/V/P
        const float* Kg = Kg0 + (size_t)kt0 * HDM;
        const float* Vg = Vg0 + (size_t)kt0 * (NKV * HDM);
        for (int idx = tid; idx < 1024; idx += 256) {
            int c = idx >> 4, d = (idx & 15) << 2;
            float4 kv = *(const float4*)(Kg + c * HDM + d);
            Kt[(d+0)*64 + c] = kv.x; Kt[(d+1)*64 + c] = kv.y;
            Kt[(d+2)*64 + c] = kv.z; Kt[(d+3)*64 + c] = kv.w;
            *(float4*)&Vs[c * 64 + d] = *(const float4*)(Vg + c * (NKV * HDM) + d);
        }
        __syncthreads();

        // S = Q K^T (scale folded into q)
        float s4[4][4] = {};
#pragma unroll 16
        for (int d = 0; d < 64; d++) {
            float4 qv = *(const float4*)&Qt[d * 64 + (trow << 2)];
            float4 kv = *(const float4*)&Kt[d * 64 + (tcol << 2)];
            float qa[4] = {qv.x, qv.y, qv.z, qv.w};
            float ka[4] = {kv.x, kv.y, kv.z, kv.w};
#pragma unroll
            for (int i = 0; i < 4; i++)
#pragma unroll
                for (int j = 0; j < 4; j++)
                    s4[i][j] += qa[i] * ka[j];
        }

        // mask + online softmax (row groups of 16 lanes share trow)
        const int kb = kt0 + (tcol << 2);
#pragma unroll
        for (int i = 0; i < 4; i++) {
            int q = qrow + i;
#pragma unroll
            for (int j = 0; j < 4; j++) {
                int kk = kb + j;
                if (kk > q || q - kk >= WIN) s4[i][j] = -1e30f;
            }
            float t = fmaxf(fmaxf(s4[i][0], s4[i][1]), fmaxf(s4[i][2], s4[i][3]));
#pragma unroll
            for (int o = 1; o < 16; o <<= 1)
                t = fmaxf(t, __shfl_xor_sync(0xffffffffu, t, o));
            float mn  = fmaxf(m[i], t);
            float fac = __expf(m[i] - mn);
            m[i] = mn;
            float su = 0.f;
#pragma unroll
            for (int j = 0; j < 4; j++) {
                float p = (s4[i][j] > -1e29f) ? __expf(s4[i][j] - mn) : 0.f;
                s4[i][j] = p;
                su += p;
            }
#pragma unroll
            for (int o = 1; o < 16; o <<= 1)
                su += __shfl_xor_sync(0xffffffffu, su, o);
            l[i] = l[i] * fac + su;
#pragma unroll
            for (int j = 0; j < 4; j++) O[i][j] *= fac;
        }

        // stage P (row-major, stride 68, float4 writes conflict-free)
#pragma unroll
        for (int i = 0; i < 4; i++)
            *(float4*)&Ps[((trow << 2) + i) * 68 + (tcol << 2)] =
                make_float4(s4[i][0], s4[i][1], s4[i][2], s4[i][3]);
        __syncthreads();

        // O += P V
#pragma unroll 8
        for (int c = 0; c < 64; c++) {
            float4 vv = *(const float4*)&Vs[c * 64 + (tcol << 2)];
            float va[4] = {vv.x, vv.y, vv.z, vv.w};
            float pa[4];
#pragma unroll
            for (int i = 0; i < 4; i++) pa[i] = Ps[((trow << 2) + i) * 68 + c];
#pragma unroll
            for (int i = 0; i < 4; i++)
#pragma unroll
                for (int j = 0; j < 4; j++)
                    O[i][j] += pa[i] * va[j];
        }
    }

    float* Yg = g_y + ((size_t)(b * NH + h) * SEQ + qrow) * HDM + (tcol << 2);
#pragma unroll
    for (int i = 0; i < 4; i++) {
        float inv = 1.f / l[i];
        *(float4*)(Yg + (size_t)i * HDM) =
            make_float4(O[i][0]*inv, O[i][1]*inv, O[i][2]*inv, O[i][3]*inv);
    }
}

// ---------------- pair mix:  y_out[2p+o] = sum_i pm[p][o][i]*y[2p+i] ------
__global__ __launch_bounds__(256) void pairmix_kernel(const float* __restrict__ pm)
{
    int idx = blockIdx.x * 256 + threadIdx.x;   // over BSZ*SEQ*EMB
    int d  = idx & 63;
    int h  = (idx >> 6) & 15;
    int bs = idx >> 10;
    int b  = bs >> 11;
    int s  = bs & (SEQ - 1);
    int p  = h >> 1, o = h & 1;
    size_t base = ((size_t)(b * NH + (p << 1)) * SEQ + s) * HDM + d;
    float y0 = g_y[base];
    float y1 = g_y[base + (size_t)SEQ * HDM];
    g_ymix[idx] = pm[(p << 2) + (o << 1)] * y0 + pm[(p << 2) + (o << 1) + 1] * y1;
}

// ---------------- launch ----------------
extern "C" void kernel_launch(void* const* d_in, const int* in_sizes, int n_in,
                              void* d_out, int out_size)
{
    const float* x     = (const float*)d_in[0];
    const float* Wq    = (const float*)d_in[1];
    const float* Wk    = (const float*)d_in[2];
    const float* Wv    = (const float*)d_in[3];
    const float* Wo    = (const float*)d_in[4];
    const float* qgain = (const float*)d_in[5];
    const float* pm    = (const float*)d_in[6];
    float* out = (float*)d_out;

    void *qp, *kp, *vp, *ymix;
    cudaGetSymbolAddress(&qp,   g_qp);
    cudaGetSymbolAddress(&kp,   g_kp);
    cudaGetSymbolAddress(&vp,   g_vp);
    cudaGetSymbolAddress(&ymix, g_ymix);

    const int ATTN_SMEM = (4096 * 3 + 64 * 68) * 4;   // 66560 B
    cudaFuncSetAttribute(attn_kernel, cudaFuncAttributeMaxDynamicSharedMemorySize,
                         ATTN_SMEM);

    const int M = BSZ * SEQ;                 // 4096

    rope_table_kernel<<<SEQ * 32 / 256, 256>>>();
    gemm64<<<dim3(EMB / 64, M / 64), 256>>>(x, Wq, (float*)qp, M, EMB, EMB);
    gemm64<<<dim3(NKV * HDM / 64, M / 64), 256>>>(x, Wk, (float*)kp, M, NKV * HDM, EMB);
    gemm64<<<dim3(NKV * HDM / 64, M / 64), 256>>>(x, Wv, (float*)vp, M, NKV * HDM, EMB);
    prep_kernel<<<(BSZ * SEQ * (NH + NKV) * 32) / 256, 256>>>(qgain);
    attn_kernel<<<dim3(SEQ / 64, BSZ * NH), 256, ATTN_SMEM>>>();
    pairmix_kernel<<<(BSZ * SEQ * EMB) / 256, 256>>>(pm);
    gemm64<<<dim3(EMB / 64, M / 64), 256>>>((const float*)ymix, Wo, out, M, EMB, EMB);
}

// round 9
// speedup vs baseline: 1.9823x; 1.9759x over previous
#include <cuda_runtime.h>
#include <math.h>

#define BSZ 2
#define SEQ 2048
#define EMB 1024
#define NH  16
#define NKV 4
#define HDM 64
#define WIN 256

// ---------------- scratch (no allocations allowed) ----------------
__device__ float g_qp[BSZ*SEQ*EMB];        // x @ Wq^T
__device__ float g_kp[BSZ*SEQ*NKV*HDM];    // x @ Wk^T
__device__ float g_vp[BSZ*SEQ*NKV*HDM];    // x @ Wv^T
__device__ float g_q [BSZ*NH*SEQ*HDM];     // normed+roped+scaled q  [b][h][s][d]
__device__ float g_k [BSZ*NKV*SEQ*HDM];    // normed+roped k         [b][g][s][d]
__device__ float g_y [BSZ*NH*SEQ*HDM];     // attention out          [b][h][s][d]
__device__ float g_ymix[BSZ*SEQ*EMB];      // pair-mixed, [b][s][h*64+d]
__device__ float g_cos[SEQ*32];
__device__ float g_sin[SEQ*32];

// ---------------- rope tables (double precision) ----------------
__global__ void rope_table_kernel() {
    int idx = blockIdx.x * blockDim.x + threadIdx.x;
    if (idx >= SEQ * 32) return;
    int s = idx >> 5, l = idx & 31;
    double inv = exp(-(double)l * (9.210340371976184 / 32.0)); // ln(10000)
    double a = (double)s * inv;
    g_cos[idx] = (float)cos(a);
    g_sin[idx] = (float)sin(a);
}

// ---------------- tf32 tensor-core GEMM ----------------
// C[M,N] = A[M,K] @ W[N,K]^T, both row-major K-contiguous.
// 128x128 block tile, BK=16, 256 threads = 8 warps (2x4), warp tile 64x32.
// mma.sync.m16n8k8 tf32. Smem uses k-interleaved layout so that each
// fragment load is a single LDS.64 (pairs (k, k+4) adjacent), row stride 24
// floats => conflict-free for both frag loads.
//   col(kl) = 8*(kl>>3) + 2*(kl&3) + ((kl>>2)&1)
#define SSTR 24

__device__ __forceinline__ unsigned f2tf32(float f) {
    unsigned o;
    asm("cvt.rna.tf32.f32 %0, %1;" : "=r"(o) : "f"(f));
    return o;
}

__global__ __launch_bounds__(256) void gemm_tc(
    const float* __restrict__ A,
    const float* __restrict__ W,  float* __restrict__ C,
    const float* __restrict__ W2, float* __restrict__ C2,
    int M, int N, int K)
{
    if (blockIdx.z) { W = W2; C = C2; }

    __shared__ unsigned sA[128 * SSTR];
    __shared__ unsigned sW[128 * SSTR];

    const int t    = threadIdx.x;
    const int lane = t & 31, warp = t >> 5;
    const int wm = warp >> 2, wn = warp & 3;        // warp grid 2x4
    const int gr = lane >> 2, tg = lane & 3;
    const int m0 = blockIdx.y << 7, n0 = blockIdx.x << 7;

    // gmem staging coords: thread loads rows (ar, ar+64), 4 consecutive k
    const int ar = t >> 2;
    const int ac = (t & 3) << 2;
    const float* Ap = A + (size_t)(m0 + ar) * K + ac;
    const float* Wp = W + (size_t)(n0 + ar) * K + ac;

    // smem columns for the 4 staged k values (k = ac..ac+3)
    int scol[4];
#pragma unroll
    for (int j = 0; j < 4; j++) {
        int kl = ac + j;
        scol[j] = ((kl >> 3) << 3) + ((kl & 3) << 1) + ((kl >> 2) & 1);
    }

    float c[4][4][4] = {};

    float4 a0v = *(const float4*)(Ap);
    float4 a1v = *(const float4*)(Ap + (size_t)64 * K);
    float4 w0v = *(const float4*)(Wp);
    float4 w1v = *(const float4*)(Wp + (size_t)64 * K);

    for (int k0 = 16; ; k0 += 16) {
        __syncthreads();
        {
            float av0[4] = {a0v.x, a0v.y, a0v.z, a0v.w};
            float av1[4] = {a1v.x, a1v.y, a1v.z, a1v.w};
            float wv0[4] = {w0v.x, w0v.y, w0v.z, w0v.w};
            float wv1[4] = {w1v.x, w1v.y, w1v.z, w1v.w};
#pragma unroll
            for (int j = 0; j < 4; j++) {
                sA[ar * SSTR + scol[j]]        = f2tf32(av0[j]);
                sA[(ar + 64) * SSTR + scol[j]] = f2tf32(av1[j]);
                sW[ar * SSTR + scol[j]]        = f2tf32(wv0[j]);
                sW[(ar + 64) * SSTR + scol[j]] = f2tf32(wv1[j]);
            }
        }
        __syncthreads();

        if (k0 < K) {
            a0v = *(const float4*)(Ap + k0);
            a1v = *(const float4*)(Ap + (size_t)64 * K + k0);
            w0v = *(const float4*)(Wp + k0);
            w1v = *(const float4*)(Wp + (size_t)64 * K + k0);
        }

#pragma unroll
        for (int kk = 0; kk < 2; kk++) {
            unsigned a[4][4];   // [mi][a0..a3]
            unsigned b[4][2];   // [ni][b0,b1]
            const int kb = (kk << 3) + (tg << 1);
#pragma unroll
            for (int mi = 0; mi < 4; mi++) {
                int r = (wm << 6) + (mi << 4) + gr;
                uint2 lo = *(const uint2*)&sA[r * SSTR + kb];        // a0,a2
                uint2 hi = *(const uint2*)&sA[(r + 8) * SSTR + kb];  // a1,a3
                a[mi][0] = lo.x; a[mi][1] = hi.x; a[mi][2] = lo.y; a[mi][3] = hi.y;
            }
#pragma unroll
            for (int ni = 0; ni < 4; ni++) {
                int n = (wn << 5) + (ni << 3) + gr;
                uint2 bv = *(const uint2*)&sW[n * SSTR + kb];        // b0,b1
                b[ni][0] = bv.x; b[ni][1] = bv.y;
            }
#pragma unroll
            for (int mi = 0; mi < 4; mi++)
#pragma unroll
                for (int ni = 0; ni < 4; ni++)
                    asm volatile(
                        "mma.sync.aligned.m16n8k8.row.col.f32.tf32.tf32.f32 "
                        "{%0,%1,%2,%3}, {%4,%5,%6,%7}, {%8,%9}, {%0,%1,%2,%3};"
                        : "+f"(c[mi][ni][0]), "+f"(c[mi][ni][1]),
                          "+f"(c[mi][ni][2]), "+f"(c[mi][ni][3])
                        : "r"(a[mi][0]), "r"(a[mi][1]), "r"(a[mi][2]), "r"(a[mi][3]),
                          "r"(b[ni][0]), "r"(b[ni][1]));
        }
        if (k0 >= K) break;
    }

    // epilogue: c0,c1 at (row gr, cols 2tg,2tg+1); c2,c3 at row gr+8
#pragma unroll
    for (int mi = 0; mi < 4; mi++) {
#pragma unroll
        for (int ni = 0; ni < 4; ni++) {
            int row = m0 + (wm << 6) + (mi << 4) + gr;
            int col = n0 + (wn << 5) + (ni << 3) + (tg << 1);
            *(float2*)&C[(size_t)row * N + col] =
                make_float2(c[mi][ni][0], c[mi][ni][1]);
            *(float2*)&C[(size_t)(row + 8) * N + col] =
                make_float2(c[mi][ni][2], c[mi][ni][3]);
        }
    }
}

// ---------------- rmsnorm + rope + gain  (one warp per head-vector) -------
__global__ __launch_bounds__(256) void prep_kernel(const float* __restrict__ qgain)
{
    const int gw   = (blockIdx.x * 256 + threadIdx.x) >> 5;
    const int lane = threadIdx.x & 31;
    const int NQ = BSZ * SEQ * NH;          // 65536
    const int NK = BSZ * SEQ * NKV;         // 16384

    const float* in; float* out; float extra; int s;
    if (gw < NQ) {
        int h = gw & 15; int bs = gw >> 4;
        s = bs & (SEQ - 1); int b = bs >> 11;
        in  = g_qp + (size_t)bs * EMB + h * HDM;
        out = g_q  + ((size_t)(b * NH + h) * SEQ + s) * HDM;
        extra = qgain[h] * 0.125f;          // fold 1/sqrt(64) attention scale
    } else {
        int kw = gw - NQ;
        if (kw >= NK) return;
        int g = kw & 3; int bs = kw >> 2;
        s = bs & (SEQ - 1); int b = bs >> 11;
        in  = g_kp + (size_t)bs * (NKV * HDM) + g * HDM;
        out = g_k  + ((size_t)(b * NKV + g) * SEQ + s) * HDM;
        extra = 1.f;
    }
    float v1 = in[lane], v2 = in[lane + 32];
    float ss = v1 * v1 + v2 * v2;
#pragma unroll
    for (int o = 16; o; o >>= 1) ss += __shfl_xor_sync(0xffffffffu, ss, o);
    float r = rsqrtf(ss * (1.f / HDM) + 1e-6f) * extra;
    float c  = g_cos[s * 32 + lane];
    float sn = g_sin[s * 32 + lane];
    out[lane]      = (v1 * c + v2 * sn) * r;
    out[lane + 32] = (v2 * c - v1 * sn) * r;
}

// ---------------- windowed flash attention ----------------
__global__ __launch_bounds__(256) void attn_kernel()
{
    extern __shared__ float sm[];
    float* Qt = sm;            // Qt[d*64 + r]
    float* Kt = sm + 4096;     // Kt[d*64 + c]
    float* Vs = sm + 8192;     // Vs[c*64 + dv]
    float* Ps = sm + 12288;    // Ps[r*68 + c]

    const int tid  = threadIdx.x;
    const int trow = tid >> 4, tcol = tid & 15;
    const int bh = blockIdx.y;
    const int b = bh >> 4, h = bh & 15, g = h >> 2;
    const int q0 = blockIdx.x << 6;

    const float* Qg = g_q + ((size_t)(b * NH + h) * SEQ + q0) * HDM;
    for (int idx = tid; idx < 1024; idx += 256) {
        int r = idx >> 4, d = (idx & 15) << 2;
        float4 v = *(const float4*)(Qg + r * HDM + d);
        Qt[(d+0)*64 + r] = v.x; Qt[(d+1)*64 + r] = v.y;
        Qt[(d+2)*64 + r] = v.z; Qt[(d+3)*64 + r] = v.w;
    }

    float m[4], l[4], O[4][4];
#pragma unroll
    for (int i = 0; i < 4; i++) {
        m[i] = -1e30f; l[i] = 0.f;
#pragma unroll
        for (int j = 0; j < 4; j++) O[i][j] = 0.f;
    }
    const int qrow = q0 + (trow << 2);
    const float* Kg0 = g_k  + (size_t)(b * NKV + g) * SEQ * HDM;
    const float* Vg0 = g_vp + (size_t)b * SEQ * (NKV * HDM) + g * HDM;

    for (int kt0 = q0 - 256; kt0 <= q0; kt0 += 64) {
        if (kt0 < 0) continue;
        __syncthreads();
        const float* Kg = Kg0 + (size_t)kt0 * HDM;
        const float* Vg = Vg0 + (size_t)kt0 * (NKV * HDM);
        for (int idx = tid; idx < 1024; idx += 256) {
            int c = idx >> 4, d = (idx & 15) << 2;
            float4 kv = *(const float4*)(Kg + c * HDM + d);
            Kt[(d+0)*64 + c] = kv.x; Kt[(d+1)*64 + c] = kv.y;
            Kt[(d+2)*64 + c] = kv.z; Kt[(d+3)*64 + c] = kv.w;
            *(float4*)&Vs[c * 64 + d] = *(const float4*)(Vg + c * (NKV * HDM) + d);
        }
        __syncthreads();

        float s4[4][4] = {};
#pragma unroll 16
        for (int d = 0; d < 64; d++) {
            float4 qv = *(const float4*)&Qt[d * 64 + (trow << 2)];
            float4 kv = *(const float4*)&Kt[d * 64 + (tcol << 2)];
            float qa[4] = {qv.x, qv.y, qv.z, qv.w};
            float ka[4] = {kv.x, kv.y, kv.z, kv.w};
#pragma unroll
            for (int i = 0; i < 4; i++)
#pragma unroll
                for (int j = 0; j < 4; j++)
                    s4[i][j] += qa[i] * ka[j];
        }

        const int kb = kt0 + (tcol << 2);
#pragma unroll
        for (int i = 0; i < 4; i++) {
            int q = qrow + i;
#pragma unroll
            for (int j = 0; j < 4; j++) {
                int kk = kb + j;
                if (kk > q || q - kk >= WIN) s4[i][j] = -1e30f;
            }
            float t = fmaxf(fmaxf(s4[i][0], s4[i][1]), fmaxf(s4[i][2], s4[i][3]));
#pragma unroll
            for (int o = 1; o < 16; o <<= 1)
                t = fmaxf(t, __shfl_xor_sync(0xffffffffu, t, o));
            float mn  = fmaxf(m[i], t);
            float fac = __expf(m[i] - mn);
            m[i] = mn;
            float su = 0.f;
#pragma unroll
            for (int j = 0; j < 4; j++) {
                float p = (s4[i][j] > -1e29f) ? __expf(s4[i][j] - mn) : 0.f;
                s4[i][j] = p;
                su += p;
            }
#pragma unroll
            for (int o = 1; o < 16; o <<= 1)
                su += __shfl_xor_sync(0xffffffffu, su, o);
            l[i] = l[i] * fac + su;
#pragma unroll
            for (int j = 0; j < 4; j++) O[i][j] *= fac;
        }

#pragma unroll
        for (int i = 0; i < 4; i++)
            *(float4*)&Ps[((trow << 2) + i) * 68 + (tcol << 2)] =
                make_float4(s4[i][0], s4[i][1], s4[i][2], s4[i][3]);
        __syncthreads();

#pragma unroll 8
        for (int c = 0; c < 64; c++) {
            float4 vv = *(const float4*)&Vs[c * 64 + (tcol << 2)];
            float va[4] = {vv.x, vv.y, vv.z, vv.w};
            float pa[4];
#pragma unroll
            for (int i = 0; i < 4; i++) pa[i] = Ps[((trow << 2) + i) * 68 + c];
#pragma unroll
            for (int i = 0; i < 4; i++)
#pragma unroll
                for (int j = 0; j < 4; j++)
                    O[i][j] += pa[i] * va[j];
        }
    }

    float* Yg = g_y + ((size_t)(b * NH + h) * SEQ + qrow) * HDM + (tcol << 2);
#pragma unroll
    for (int i = 0; i < 4; i++) {
        float inv = 1.f / l[i];
        *(float4*)(Yg + (size_t)i * HDM) =
            make_float4(O[i][0]*inv, O[i][1]*inv, O[i][2]*inv, O[i][3]*inv);
    }
}

// ---------------- pair mix ----------------
__global__ __launch_bounds__(256) void pairmix_kernel(const float* __restrict__ pm)
{
    int idx = blockIdx.x * 256 + threadIdx.x;
    int d  = idx & 63;
    int h  = (idx >> 6) & 15;
    int bs = idx >> 10;
    int b  = bs >> 11;
    int s  = bs & (SEQ - 1);
    int p  = h >> 1, o = h & 1;
    size_t base = ((size_t)(b * NH + (p << 1)) * SEQ + s) * HDM + d;
    float y0 = g_y[base];
    float y1 = g_y[base + (size_t)SEQ * HDM];
    g_ymix[idx] = pm[(p << 2) + (o << 1)] * y0 + pm[(p << 2) + (o << 1) + 1] * y1;
}

// ---------------- launch ----------------
extern "C" void kernel_launch(void* const* d_in, const int* in_sizes, int n_in,
                              void* d_out, int out_size)
{
    const float* x     = (const float*)d_in[0];
    const float* Wq    = (const float*)d_in[1];
    const float* Wk    = (const float*)d_in[2];
    const float* Wv    = (const float*)d_in[3];
    const float* Wo    = (const float*)d_in[4];
    const float* qgain = (const float*)d_in[5];
    const float* pm    = (const float*)d_in[6];
    float* out = (float*)d_out;

    void *qp, *kp, *vp, *ymix;
    cudaGetSymbolAddress(&qp,   g_qp);
    cudaGetSymbolAddress(&kp,   g_kp);
    cudaGetSymbolAddress(&vp,   g_vp);
    cudaGetSymbolAddress(&ymix, g_ymix);

    const int ATTN_SMEM = (4096 * 3 + 64 * 68) * 4;   // 66560 B
    cudaFuncSetAttribute(attn_kernel, cudaFuncAttributeMaxDynamicSharedMemorySize,
                         ATTN_SMEM);

    const int M = BSZ * SEQ;                 // 4096

    rope_table_kernel<<<SEQ * 32 / 256, 256>>>();
    // Q projection: N=1024
    gemm_tc<<<dim3(EMB / 128, M / 128, 1), 256>>>(
        x, Wq, (float*)qp, Wq, (float*)qp, M, EMB, EMB);
    // K and V projections fused on grid.z: N=256 each
    gemm_tc<<<dim3(NKV * HDM / 128, M / 128, 2), 256>>>(
        x, Wk, (float*)kp, Wv, (float*)vp, M, NKV * HDM, EMB);
    prep_kernel<<<(BSZ * SEQ * (NH + NKV) * 32) / 256, 256>>>(qgain);
    attn_kernel<<<dim3(SEQ / 64, BSZ * NH), 256, ATTN_SMEM>>>();
    pairmix_kernel<<<(BSZ * SEQ * EMB) / 256, 256>>>(pm);
    // output projection
    gemm_tc<<<dim3(EMB / 128, M / 128, 1), 256>>>(
        (const float*)ymix, Wo, out, Wo, out, M, EMB, EMB);
}

// round 10
// speedup vs baseline: 2.6308x; 1.3272x over previous
#include <cuda_runtime.h>
#include <math.h>

#define BSZ 2
#define SEQ 2048
#define EMB 1024
#define NH  16
#define NKV 4
#define HDM 64
#define WIN 256

// ---------------- scratch (no allocations allowed) ----------------
__device__ float g_qp[BSZ*SEQ*EMB];        // x @ Wq^T
__device__ float g_kp[BSZ*SEQ*NKV*HDM];    // x @ Wk^T
__device__ float g_vp[BSZ*SEQ*NKV*HDM];    // x @ Wv^T
__device__ float g_q [BSZ*NH*SEQ*HDM];     // normed+roped+scaled q  [b][h][s][d]
__device__ float g_k [BSZ*NKV*SEQ*HDM];    // normed+roped k         [b][g][s][d]
__device__ float g_y [BSZ*SEQ*NH*HDM];     // attention out [b][s][h][d]
__device__ float g_ymix[BSZ*SEQ*EMB];      // pair-mixed, [b][s][h*64+d]
__device__ float g_cos[SEQ*32];
__device__ float g_sin[SEQ*32];

// ---------------- rope tables (double precision) ----------------
__global__ void rope_table_kernel() {
    int idx = blockIdx.x * blockDim.x + threadIdx.x;
    if (idx >= SEQ * 32) return;
    int s = idx >> 5, l = idx & 31;
    double inv = exp(-(double)l * (9.210340371976184 / 32.0)); // ln(10000)
    double a = (double)s * inv;
    g_cos[idx] = (float)cos(a);
    g_sin[idx] = (float)sin(a);
}

__device__ __forceinline__ unsigned f2tf32(float f) {
    unsigned o;
    asm("cvt.rna.tf32.f32 %0, %1;" : "=r"(o) : "f"(f));
    return o;
}

#define MMA_TF32(c, a, b)                                                     \
    asm volatile(                                                             \
        "mma.sync.aligned.m16n8k8.row.col.f32.tf32.tf32.f32 "                 \
        "{%0,%1,%2,%3}, {%4,%5,%6,%7}, {%8,%9}, {%0,%1,%2,%3};"               \
        : "+f"((c)[0]), "+f"((c)[1]), "+f"((c)[2]), "+f"((c)[3])              \
        : "r"((a)[0]), "r"((a)[1]), "r"((a)[2]), "r"((a)[3]),                 \
          "r"((b)[0]), "r"((b)[1]))

// ---------------- tf32 tensor-core GEMM ----------------
// C[M,N] = A[M,K] @ W[N,K]^T. 128x128 tile, BK=16, 8 warps, warp 64x32.
#define SSTR 24

__global__ __launch_bounds__(256) void gemm_tc(
    const float* __restrict__ A,
    const float* __restrict__ W,  float* __restrict__ C,
    const float* __restrict__ W2, float* __restrict__ C2,
    int M, int N, int K)
{
    if (blockIdx.z) { W = W2; C = C2; }

    __shared__ unsigned sA[128 * SSTR];
    __shared__ unsigned sW[128 * SSTR];

    const int t    = threadIdx.x;
    const int lane = t & 31, warp = t >> 5;
    const int wm = warp >> 2, wn = warp & 3;
    const int gr = lane >> 2, tg = lane & 3;
    const int m0 = blockIdx.y << 7, n0 = blockIdx.x << 7;

    const int ar = t >> 2;
    const int ac = (t & 3) << 2;
    const float* Ap = A + (size_t)(m0 + ar) * K + ac;
    const float* Wp = W + (size_t)(n0 + ar) * K + ac;

    int scol[4];
#pragma unroll
    for (int j = 0; j < 4; j++) {
        int kl = ac + j;
        scol[j] = ((kl >> 3) << 3) + ((kl & 3) << 1) + ((kl >> 2) & 1);
    }

    float c[4][4][4] = {};

    float4 a0v = *(const float4*)(Ap);
    float4 a1v = *(const float4*)(Ap + (size_t)64 * K);
    float4 w0v = *(const float4*)(Wp);
    float4 w1v = *(const float4*)(Wp + (size_t)64 * K);

    for (int k0 = 16; ; k0 += 16) {
        __syncthreads();
        {
            float av0[4] = {a0v.x, a0v.y, a0v.z, a0v.w};
            float av1[4] = {a1v.x, a1v.y, a1v.z, a1v.w};
            float wv0[4] = {w0v.x, w0v.y, w0v.z, w0v.w};
            float wv1[4] = {w1v.x, w1v.y, w1v.z, w1v.w};
#pragma unroll
            for (int j = 0; j < 4; j++) {
                sA[ar * SSTR + scol[j]]        = f2tf32(av0[j]);
                sA[(ar + 64) * SSTR + scol[j]] = f2tf32(av1[j]);
                sW[ar * SSTR + scol[j]]        = f2tf32(wv0[j]);
                sW[(ar + 64) * SSTR + scol[j]] = f2tf32(wv1[j]);
            }
        }
        __syncthreads();

        if (k0 < K) {
            a0v = *(const float4*)(Ap + k0);
            a1v = *(const float4*)(Ap + (size_t)64 * K + k0);
            w0v = *(const float4*)(Wp + k0);
            w1v = *(const float4*)(Wp + (size_t)64 * K + k0);
        }

#pragma unroll
        for (int kk = 0; kk < 2; kk++) {
            unsigned a[4][4];
            unsigned b[4][2];
            const int kb = (kk << 3) + (tg << 1);
#pragma unroll
            for (int mi = 0; mi < 4; mi++) {
                int r = (wm << 6) + (mi << 4) + gr;
                uint2 lo = *(const uint2*)&sA[r * SSTR + kb];
                uint2 hi = *(const uint2*)&sA[(r + 8) * SSTR + kb];
                a[mi][0] = lo.x; a[mi][1] = hi.x; a[mi][2] = lo.y; a[mi][3] = hi.y;
            }
#pragma unroll
            for (int ni = 0; ni < 4; ni++) {
                int n = (wn << 5) + (ni << 3) + gr;
                uint2 bv = *(const uint2*)&sW[n * SSTR + kb];
                b[ni][0] = bv.x; b[ni][1] = bv.y;
            }
#pragma unroll
            for (int mi = 0; mi < 4; mi++)
#pragma unroll
                for (int ni = 0; ni < 4; ni++)
                    MMA_TF32(c[mi][ni], a[mi], b[ni]);
        }
        if (k0 >= K) break;
    }

#pragma unroll
    for (int mi = 0; mi < 4; mi++) {
#pragma unroll
        for (int ni = 0; ni < 4; ni++) {
            int row = m0 + (wm << 6) + (mi << 4) + gr;
            int col = n0 + (wn << 5) + (ni << 3) + (tg << 1);
            *(float2*)&C[(size_t)row * N + col] =
                make_float2(c[mi][ni][0], c[mi][ni][1]);
            *(float2*)&C[(size_t)(row + 8) * N + col] =
                make_float2(c[mi][ni][2], c[mi][ni][3]);
        }
    }
}

// ---------------- rmsnorm + rope + gain ----------------
__global__ __launch_bounds__(256) void prep_kernel(const float* __restrict__ qgain)
{
    const int gw   = (blockIdx.x * 256 + threadIdx.x) >> 5;
    const int lane = threadIdx.x & 31;
    const int NQ = BSZ * SEQ * NH;
    const int NK = BSZ * SEQ * NKV;

    const float* in; float* out; float extra; int s;
    if (gw < NQ) {
        int h = gw & 15; int bs = gw >> 4;
        s = bs & (SEQ - 1); int b = bs >> 11;
        in  = g_qp + (size_t)bs * EMB + h * HDM;
        out = g_q  + ((size_t)(b * NH + h) * SEQ + s) * HDM;
        extra = qgain[h] * 0.125f;
    } else {
        int kw = gw - NQ;
        if (kw >= NK) return;
        int g = kw & 3; int bs = kw >> 2;
        s = bs & (SEQ - 1); int b = bs >> 11;
        in  = g_kp + (size_t)bs * (NKV * HDM) + g * HDM;
        out = g_k  + ((size_t)(b * NKV + g) * SEQ + s) * HDM;
        extra = 1.f;
    }
    float v1 = in[lane], v2 = in[lane + 32];
    float ss = v1 * v1 + v2 * v2;
#pragma unroll
    for (int o = 16; o; o >>= 1) ss += __shfl_xor_sync(0xffffffffu, ss, o);
    float r = rsqrtf(ss * (1.f / HDM) + 1e-6f) * extra;
    float c  = g_cos[s * 32 + lane];
    float sn = g_sin[s * 32 + lane];
    out[lane]      = (v1 * c + v2 * sn) * r;
    out[lane + 32] = (v2 * c - v1 * sn) * r;
}

// ---------------- tensor-core windowed flash attention ----------------
// 128 queries x 64 keys per tile. 8 warps, warp owns 16 query rows
// (warp-local online softmax). All operands tf32 in smem, row-major, stride 68.
#define ASTR 68

__global__ __launch_bounds__(256) void attn_tc()
{
    extern __shared__ unsigned smu[];
    unsigned* sQ = smu;                    // [128][68]
    unsigned* sK = sQ + 128 * ASTR;        // [64][68]   rows = key, cols = d
    unsigned* sV = sK + 64 * ASTR;         // [64][68]   rows = key, cols = d
    unsigned* sP = sV + 64 * ASTR;         // [128][68]  rows = q,   cols = key

    const int tid  = threadIdx.x;
    const int lane = tid & 31, w = tid >> 5;
    const int gr = lane >> 2, tg = lane & 3;
    const int bh = blockIdx.y;
    const int b = bh >> 4, h = bh & 15, g = h >> 2;
    const int q0 = blockIdx.x << 7;

    // stage Q tile as tf32
    const float* Qg = g_q + ((size_t)(b * NH + h) * SEQ + q0) * HDM;
    for (int i = tid; i < 128 * 16; i += 256) {
        int r = i >> 4, d4 = (i & 15) << 2;
        float4 v = *(const float4*)(Qg + r * HDM + d4);
        unsigned* dst = sQ + r * ASTR + d4;
        dst[0] = f2tf32(v.x); dst[1] = f2tf32(v.y);
        dst[2] = f2tf32(v.z); dst[3] = f2tf32(v.w);
    }

    float m0 = -1e30f, m1 = -1e30f, l0 = 0.f, l1 = 0.f;
    float O[8][4];
#pragma unroll
    for (int ni = 0; ni < 8; ni++)
#pragma unroll
        for (int j = 0; j < 4; j++) O[ni][j] = 0.f;

    const int qw = q0 + (w << 4);        // warp's first q row
    const int qr0 = qw + gr;             // rows qr0 and qr0+8

    const float* Kg0 = g_k  + (size_t)(b * NKV + g) * SEQ * HDM;
    const float* Vg0 = g_vp + (size_t)b * SEQ * (NKV * HDM) + g * HDM;

    for (int kt0 = q0 - 256; kt0 <= q0 + 64; kt0 += 64) {
        if (kt0 < 0) continue;
        __syncthreads();
        const float* Kg = Kg0 + (size_t)kt0 * HDM;
        const float* Vg = Vg0 + (size_t)kt0 * (NKV * HDM);
        for (int i = tid; i < 64 * 16; i += 256) {
            int r = i >> 4, d4 = (i & 15) << 2;
            float4 kv = *(const float4*)(Kg + r * HDM + d4);
            unsigned* dk = sK + r * ASTR + d4;
            dk[0] = f2tf32(kv.x); dk[1] = f2tf32(kv.y);
            dk[2] = f2tf32(kv.z); dk[3] = f2tf32(kv.w);
            float4 vv = *(const float4*)(Vg + r * (NKV * HDM) + d4);
            unsigned* dv = sV + r * ASTR + d4;
            dv[0] = f2tf32(vv.x); dv[1] = f2tf32(vv.y);
            dv[2] = f2tf32(vv.z); dv[3] = f2tf32(vv.w);
        }
        __syncthreads();

        if (kt0 > qw + 15) continue;      // whole warp masked (warp-uniform)

        // ---- S = Q K^T ----
        float c[8][4] = {};
#pragma unroll
        for (int kk = 0; kk < 8; kk++) {
            const int kb = (kk << 3) + tg;
            unsigned a[4];
            a[0] = sQ[(qw - q0 + gr) * ASTR + kb];
            a[1] = sQ[(qw - q0 + gr + 8) * ASTR + kb];
            a[2] = sQ[(qw - q0 + gr) * ASTR + kb + 4];
            a[3] = sQ[(qw - q0 + gr + 8) * ASTR + kb + 4];
#pragma unroll
            for (int ni = 0; ni < 8; ni++) {
                unsigned bb[2];
                bb[0] = sK[((ni << 3) + gr) * ASTR + kb];
                bb[1] = sK[((ni << 3) + gr) * ASTR + kb + 4];
                MMA_TF32(c[ni], a, bb);
            }
        }

        // ---- mask + warp-local online softmax ----
        const bool full = (kt0 + 63 <= qw) && (qw + 15 - kt0 < WIN);
        float rx0 = -1e30f, rx1 = -1e30f;
#pragma unroll
        for (int ni = 0; ni < 8; ni++) {
            if (!full) {
                int c0 = kt0 + (ni << 3) + (tg << 1);
                int q_0 = qr0, q_1 = qr0 + 8;
                if (c0 > q_0   || q_0 - c0 >= WIN)     c[ni][0] = -1e30f;
                if (c0+1 > q_0 || q_0 - (c0+1) >= WIN) c[ni][1] = -1e30f;
                if (c0 > q_1   || q_1 - c0 >= WIN)     c[ni][2] = -1e30f;
                if (c0+1 > q_1 || q_1 - (c0+1) >= WIN) c[ni][3] = -1e30f;
            }
            rx0 = fmaxf(rx0, fmaxf(c[ni][0], c[ni][1]));
            rx1 = fmaxf(rx1, fmaxf(c[ni][2], c[ni][3]));
        }
        rx0 = fmaxf(rx0, __shfl_xor_sync(0xffffffffu, rx0, 1));
        rx0 = fmaxf(rx0, __shfl_xor_sync(0xffffffffu, rx0, 2));
        rx1 = fmaxf(rx1, __shfl_xor_sync(0xffffffffu, rx1, 1));
        rx1 = fmaxf(rx1, __shfl_xor_sync(0xffffffffu, rx1, 2));

        float mn0 = fmaxf(m0, rx0), mn1 = fmaxf(m1, rx1);
        float fac0 = __expf(m0 - mn0), fac1 = __expf(m1 - mn1);
        m0 = mn0; m1 = mn1;

        float s0 = 0.f, s1 = 0.f;
#pragma unroll
        for (int ni = 0; ni < 8; ni++) {
            float p0 = (c[ni][0] > -1e29f) ? __expf(c[ni][0] - mn0) : 0.f;
            float p1 = (c[ni][1] > -1e29f) ? __expf(c[ni][1] - mn0) : 0.f;
            float p2 = (c[ni][2] > -1e29f) ? __expf(c[ni][2] - mn1) : 0.f;
            float p3 = (c[ni][3] > -1e29f) ? __expf(c[ni][3] - mn1) : 0.f;
            s0 += p0 + p1; s1 += p2 + p3;
            int col = (ni << 3) + (tg << 1);
            *(uint2*)&sP[(qw - q0 + gr) * ASTR + col] =
                make_uint2(f2tf32(p0), f2tf32(p1));
            *(uint2*)&sP[(qw - q0 + gr + 8) * ASTR + col] =
                make_uint2(f2tf32(p2), f2tf32(p3));
        }
        s0 += __shfl_xor_sync(0xffffffffu, s0, 1);
        s0 += __shfl_xor_sync(0xffffffffu, s0, 2);
        s1 += __shfl_xor_sync(0xffffffffu, s1, 1);
        s1 += __shfl_xor_sync(0xffffffffu, s1, 2);
        l0 = l0 * fac0 + s0;
        l1 = l1 * fac1 + s1;
#pragma unroll
        for (int ni = 0; ni < 8; ni++) {
            O[ni][0] *= fac0; O[ni][1] *= fac0;
            O[ni][2] *= fac1; O[ni][3] *= fac1;
        }
        __syncwarp();

        // ---- O += P V ----
#pragma unroll
        for (int kk = 0; kk < 8; kk++) {
            const int kb = (kk << 3) + tg;
            unsigned a[4];
            a[0] = sP[(qw - q0 + gr) * ASTR + kb];
            a[1] = sP[(qw - q0 + gr + 8) * ASTR + kb];
            a[2] = sP[(qw - q0 + gr) * ASTR + kb + 4];
            a[3] = sP[(qw - q0 + gr + 8) * ASTR + kb + 4];
#pragma unroll
            for (int ni = 0; ni < 8; ni++) {
                unsigned bb[2];
                bb[0] = sV[kb * ASTR + (ni << 3) + gr];
                bb[1] = sV[(kb + 4) * ASTR + (ni << 3) + gr];
                MMA_TF32(O[ni], a, bb);
            }
        }
    }

    // epilogue: divide by l, write [b][s][h][d]
    float inv0 = 1.f / l0, inv1 = 1.f / l1;
#pragma unroll
    for (int ni = 0; ni < 8; ni++) {
        int col = (ni << 3) + (tg << 1);
        size_t base0 = (((size_t)b * SEQ + qr0) * NH + h) * HDM + col;
        size_t base1 = (((size_t)b * SEQ + qr0 + 8) * NH + h) * HDM + col;
        *(float2*)&g_y[base0] = make_float2(O[ni][0] * inv0, O[ni][1] * inv0);
        *(float2*)&g_y[base1] = make_float2(O[ni][2] * inv1, O[ni][3] * inv1);
    }
}

// ---------------- pair mix (coalesced over [b][s][h][d]) ----------------
__global__ __launch_bounds__(256) void pairmix_kernel(const float* __restrict__ pm)
{
    int idx = blockIdx.x * 256 + threadIdx.x;
    int d  = idx & 63;
    int h  = (idx >> 6) & 15;
    int bs = idx >> 10;
    int p  = h >> 1, o = h & 1;
    size_t base = (size_t)bs * EMB + (p << 7) + d;
    float y0 = g_y[base];
    float y1 = g_y[base + 64];
    g_ymix[idx] = pm[(p << 2) + (o << 1)] * y0 + pm[(p << 2) + (o << 1) + 1] * y1;
}

// ---------------- launch ----------------
extern "C" void kernel_launch(void* const* d_in, const int* in_sizes, int n_in,
                              void* d_out, int out_size)
{
    const float* x     = (const float*)d_in[0];
    const float* Wq    = (const float*)d_in[1];
    const float* Wk    = (const float*)d_in[2];
    const float* Wv    = (const float*)d_in[3];
    const float* Wo    = (const float*)d_in[4];
    const float* qgain = (const float*)d_in[5];
    const float* pm    = (const float*)d_in[6];
    float* out = (float*)d_out;

    void *qp, *kp, *vp, *ymix;
    cudaGetSymbolAddress(&qp,   g_qp);
    cudaGetSymbolAddress(&kp,   g_kp);
    cudaGetSymbolAddress(&vp,   g_vp);
    cudaGetSymbolAddress(&ymix, g_ymix);

    const int ATTN_SMEM = (128 + 64 + 64 + 128) * ASTR * 4;   // 104448 B
    cudaFuncSetAttribute(attn_tc, cudaFuncAttributeMaxDynamicSharedMemorySize,
                         ATTN_SMEM);

    const int M = BSZ * SEQ;                 // 4096

    rope_table_kernel<<<SEQ * 32 / 256, 256>>>();
    gemm_tc<<<dim3(EMB / 128, M / 128, 1), 256>>>(
        x, Wq, (float*)qp, Wq, (float*)qp, M, EMB, EMB);
    gemm_tc<<<dim3(NKV * HDM / 128, M / 128, 2), 256>>>(
        x, Wk, (float*)kp, Wv, (float*)vp, M, NKV * HDM, EMB);
    prep_kernel<<<(BSZ * SEQ * (NH + NKV) * 32) / 256, 256>>>(qgain);
    attn_tc<<<dim3(SEQ / 128, BSZ * NH), 256, ATTN_SMEM>>>();
    pairmix_kernel<<<(BSZ * SEQ * EMB) / 256, 256>>>(pm);
    gemm_tc<<<dim3(EMB / 128, M / 128, 1), 256>>>(
        (const float*)ymix, Wo, out, Wo, out, M, EMB, EMB);
}